// round 1
// baseline (speedup 1.0000x reference)
#include <cuda_runtime.h>
#include <cstdint>
#include <math.h>

// Problem constants
#define HDIM 256   // hidden
#define SDIM 512   // sequence
#define BDIM 2048  // batch
#define CDIM 10    // classes
#define BT   16    // batch columns per CTA
#define NCTA (BDIM / BT)   // 128
#define NTHR 256
#define KT   64            // k-tile of W per stage
#define WP   68            // Ws row pad (floats): 64 + 4, float4-aligned
#define HP   20            // h row pad (floats): 16 + 4, float4-aligned
#define XP   516           // xs row pad (floats): 512 + 4 (bank spread)

__device__ __forceinline__ uint32_t sm_addr(const void* p) {
    return (uint32_t)__cvta_generic_to_shared(p);
}
__device__ __forceinline__ void cp16(uint32_t dst, const void* src) {
    asm volatile("cp.async.ca.shared.global [%0], [%1], 16;\n" :: "r"(dst), "l"(src));
}
__device__ __forceinline__ void cp_commit() {
    asm volatile("cp.async.commit_group;\n" ::: "memory");
}
__device__ __forceinline__ void cp_wait0() {
    asm volatile("cp.async.wait_group 0;\n" ::: "memory");
}

// Persistent RNN kernel: each CTA owns BT=16 batch columns for all 512 steps.
// h state lives in SMEM (double-buffered). W_hh is streamed from L2 each step
// in 4 k-tiles of 64, double-buffered via cp.async so loads overlap compute.
// Thread tile: TM=4 rows x TN=4 cols per thread (256 threads = 256 rows x 16 cols).
extern "C" __global__ void __launch_bounds__(NTHR, 1)
rnn_persist_kernel(const float* __restrict__ x,
                   const float* __restrict__ W_hx,
                   const float* __restrict__ W_hh,
                   const float* __restrict__ W_ph,
                   const float* __restrict__ b_h,
                   const float* __restrict__ b_p,
                   float* __restrict__ out)
{
    extern __shared__ float sm[];
    float* Ws   = sm;                       // [2][HDIM][WP]  = 139264 B
    float* hbuf = Ws + 2 * HDIM * WP;       // [2][HDIM][HP]  =  40960 B
    float* xs   = hbuf + 2 * HDIM * HP;     // [BT][XP]       =  33024 B
    float* wx   = xs + BT * XP;             // [HDIM]
    float* bh   = wx + HDIM;                // [HDIM]

    const int tid = threadIdx.x;
    const int c0  = blockIdx.x * BT;        // first batch column of this CTA
    const int i0  = (tid >> 2) * 4;         // row tile base (0..252)
    const int j0  = (tid & 3) * 4;          // col tile base (0,4,8,12)

    // ---- prologue: stage x rows (coalesced float4), wx, bh, zero h ----
    {
        const int nf4 = BT * SDIM / 4;      // 2048 float4
        #pragma unroll 1
        for (int idx = tid; idx < nf4; idx += NTHR) {
            int j  = idx >> 7;              // / 128
            int t4 = idx & 127;
            float4 v = *reinterpret_cast<const float4*>(
                x + (size_t)(c0 + j) * SDIM + t4 * 4);
            *reinterpret_cast<float4*>(xs + j * XP + t4 * 4) = v;
        }
    }
    wx[tid] = W_hx[tid];
    bh[tid] = b_h[tid];
    #pragma unroll 1
    for (int idx = tid; idx < 2 * HDIM * HP; idx += NTHR) hbuf[idx] = 0.0f;

    // Preload W tile 0 into Ws buffer 0
    {
        #pragma unroll
        for (int r = 0; r < 16; ++r) {
            int idx = tid + NTHR * r;
            int i   = idx >> 4;
            int k4  = (idx & 15) * 4;
            cp16(sm_addr(Ws + i * WP + k4), W_hh + i * HDIM + k4);
        }
        cp_commit();
        cp_wait0();
    }
    __syncthreads();

    float wxr[4], bhr[4];
    #pragma unroll
    for (int r = 0; r < 4; ++r) { wxr[r] = wx[i0 + r]; bhr[r] = bh[i0 + r]; }

    int cur = 0;

    // ======================= time loop =======================
    #pragma unroll 1
    for (int t = 0; t < SDIM; ++t) {
        float acc[4][4];
        #pragma unroll
        for (int c = 0; c < 4; ++c) {
            float xv = xs[(j0 + c) * XP + t];
            #pragma unroll
            for (int r = 0; r < 4; ++r) acc[r][c] = wxr[r] * xv + bhr[r];
        }

        const float* hc = hbuf + cur * HDIM * HP;
        int buf = 0;

        #pragma unroll 1
        for (int tile = 0; tile < 4; ++tile) {
            // prefetch next k-tile (wraps to tile 0 for next step) into buf^1
            {
                int nt = (tile + 1) & 3;
                float* dst = Ws + (buf ^ 1) * HDIM * WP;
                const float* src = W_hh + nt * KT;
                #pragma unroll
                for (int r = 0; r < 16; ++r) {
                    int idx = tid + NTHR * r;
                    int i   = idx >> 4;
                    int k4  = (idx & 15) * 4;
                    cp16(sm_addr(dst + i * WP + k4), src + i * HDIM + k4);
                }
                cp_commit();
            }

            // compute 64 k's of the GEMM from Ws[buf]
            const float* wb = Ws + buf * HDIM * WP + i0 * WP;
            const float* hk = hc + tile * KT * HP + j0;
            #pragma unroll 4
            for (int kk = 0; kk < KT; kk += 4) {
                float w0[4], w1[4], w2[4], w3[4];
                *reinterpret_cast<float4*>(w0) =
                    *reinterpret_cast<const float4*>(wb + 0 * WP + kk);
                *reinterpret_cast<float4*>(w1) =
                    *reinterpret_cast<const float4*>(wb + 1 * WP + kk);
                *reinterpret_cast<float4*>(w2) =
                    *reinterpret_cast<const float4*>(wb + 2 * WP + kk);
                *reinterpret_cast<float4*>(w3) =
                    *reinterpret_cast<const float4*>(wb + 3 * WP + kk);
                #pragma unroll
                for (int s = 0; s < 4; ++s) {
                    float hv[4];
                    *reinterpret_cast<float4*>(hv) =
                        *reinterpret_cast<const float4*>(hk + (kk + s) * HP);
                    #pragma unroll
                    for (int c = 0; c < 4; ++c) {
                        acc[0][c] += w0[s] * hv[c];
                        acc[1][c] += w1[s] * hv[c];
                        acc[2][c] += w2[s] * hv[c];
                        acc[3][c] += w3[s] * hv[c];
                    }
                }
            }

            cp_wait0();       // own prefetch done
            __syncthreads();  // everyone's prefetch visible; buf reads finished
            buf ^= 1;
        }

        // tanh + write h_{t+1} into the other buffer
        float* hn = hbuf + (cur ^ 1) * HDIM * HP;
        #pragma unroll
        for (int r = 0; r < 4; ++r) {
            float4 v;
            v.x = tanhf(acc[r][0]);
            v.y = tanhf(acc[r][1]);
            v.z = tanhf(acc[r][2]);
            v.w = tanhf(acc[r][3]);
            *reinterpret_cast<float4*>(hn + (i0 + r) * HP + j0) = v;
        }
        cur ^= 1;
        __syncthreads();
    }

    // ======================= epilogue =======================
    // out[b][c] = sum_i W_ph[c][i] * h_final[i][b] + b_p[c]
    const float* hf = hbuf + cur * HDIM * HP;
    if (tid < BT * CDIM) {
        int bl = tid / CDIM;
        int c  = tid % CDIM;
        float a = b_p[c];
        #pragma unroll 4
        for (int i = 0; i < HDIM; ++i)
            a += W_ph[c * HDIM + i] * hf[i * HP + bl];
        out[(size_t)(c0 + bl) * CDIM + c] = a;
    }
}

extern "C" void kernel_launch(void* const* d_in, const int* in_sizes, int n_in,
                              void* d_out, int out_size)
{
    const float* x    = (const float*)d_in[0];
    const float* W_hx = (const float*)d_in[1];
    const float* W_hh = (const float*)d_in[2];
    const float* W_ph = (const float*)d_in[3];
    const float* b_h  = (const float*)d_in[4];
    const float* b_p  = (const float*)d_in[5];
    float* out = (float*)d_out;

    size_t smem_bytes =
        (size_t)(2 * HDIM * WP + 2 * HDIM * HP + BT * XP + 2 * HDIM) * sizeof(float);
    // 215296 B of dynamic SMEM (> 48KB default) — raise the cap (idempotent).
    cudaFuncSetAttribute(rnn_persist_kernel,
                         cudaFuncAttributeMaxDynamicSharedMemorySize,
                         (int)smem_bytes);

    rnn_persist_kernel<<<NCTA, NTHR, smem_bytes>>>(x, W_hx, W_hh, W_ph, b_h, b_p, out);
}

// round 3
// speedup vs baseline: 4.7737x; 4.7737x over previous
#include <cuda_runtime.h>
#include <cuda_bf16.h>
#include <cstdint>

// ============================ problem constants ============================
#define HDIM 256
#define SDIM 512
#define BDIM 2048
#define CDIM 10
#define BT   16                 // batch columns per CTA (N)
#define NCTA (BDIM / BT)        // 128
#define NTHR 512                // 16 warps, one m16-tile each

// ============================ SMEM layout (bytes) ==========================
// Wlo_arr: per-warp, per-k, per-lane A-fragments, 16B each:
//   [16 warps][16 ksteps][32 lanes][16B] = 131072 B, LDS.128-friendly.
#define WLO_OFF 0
#define WLO_SZ  131072
// h tiles, [k=256][n=16] bf16, row stride 48B (16B-aligned for ldmatrix):
//   hi0, lo0, hi1, lo1
#define HROW    48
#define HTILE   (HDIM * HROW)            // 12288
#define HB_OFF  WLO_SZ                   // 131072
#define HB_SZ   (4 * HTILE)              // 49152
// x staged [n=16][t=512] fp32, row pad 516 floats
#define XROW    516
#define XS_OFF  (HB_OFF + HB_SZ)         // 180224
#define XS_SZ   (BT * XROW * 4)          // 33024
#define SMEM_SZ (XS_OFF + XS_SZ)         // 213248

// ============================ device helpers ===============================
__device__ __forceinline__ uint32_t smem_u32(const void* p) {
    return (uint32_t)__cvta_generic_to_shared(p);
}

__device__ __forceinline__ void ldsm_x4_t(uint32_t* r, uint32_t addr) {
    asm volatile("ldmatrix.sync.aligned.m8n8.x4.trans.shared.b16 "
                 "{%0,%1,%2,%3}, [%4];"
                 : "=r"(r[0]), "=r"(r[1]), "=r"(r[2]), "=r"(r[3])
                 : "r"(addr));
}

__device__ __forceinline__ void mma16816(float* d, const uint32_t* a,
                                         uint32_t b0, uint32_t b1) {
    asm volatile("mma.sync.aligned.m16n8k16.row.col.f32.bf16.bf16.f32 "
                 "{%0,%1,%2,%3},{%4,%5,%6,%7},{%8,%9},{%0,%1,%2,%3};"
                 : "+f"(d[0]), "+f"(d[1]), "+f"(d[2]), "+f"(d[3])
                 : "r"(a[0]), "r"(a[1]), "r"(a[2]), "r"(a[3]),
                   "r"(b0), "r"(b1));
}

__device__ __forceinline__ uint32_t pack_bf2(__nv_bfloat16 a, __nv_bfloat16 b) {
    return (uint32_t)__bfloat16_as_ushort(a) |
           ((uint32_t)__bfloat16_as_ushort(b) << 16);
}

// split float pair into bf16-hi pair (returned) and bf16-lo pair (out param)
__device__ __forceinline__ uint32_t split2(float x, float y, uint32_t& lo) {
    __nv_bfloat16 xh = __float2bfloat16(x), yh = __float2bfloat16(y);
    float xl = x - __bfloat162float(xh), yl = y - __bfloat162float(yh);
    lo = pack_bf2(__float2bfloat16(xl), __float2bfloat16(yl));
    return pack_bf2(xh, yh);
}

__device__ __forceinline__ float tanh_fast(float x) {
    x = fminf(fmaxf(x, -10.0f), 10.0f);
    float e = __expf(2.0f * x);
    return __fdividef(e - 1.0f, e + 1.0f);
}

// ============================ kernel =======================================
extern "C" __global__ void __launch_bounds__(NTHR, 1)
rnn_hmma_kernel(const float* __restrict__ x,
                const float* __restrict__ W_hx,
                const float* __restrict__ W_hh,
                const float* __restrict__ W_ph,
                const float* __restrict__ b_h,
                const float* __restrict__ b_p,
                float* __restrict__ out)
{
    extern __shared__ char sm[];
    const uint32_t smu = smem_u32(sm);

    const int tid  = threadIdx.x;
    const int w    = tid >> 5;          // warp id / m-tile id
    const int lane = tid & 31;
    const int g    = lane >> 2;         // groupID 0..7
    const int tIG  = lane & 3;          // thread-in-group 0..3
    const int m0   = w * 16;
    const int r0   = m0 + g, r1 = r0 + 8;
    const int c0   = blockIdx.x * BT;   // first batch column of this CTA

    // ---- stage x: xs[n][t] fp32, coalesced float4 ----
    {
        float* xs = (float*)(sm + XS_OFF);
        #pragma unroll 1
        for (int idx = tid; idx < BT * SDIM / 4; idx += NTHR) {
            int n = idx >> 7, t4 = idx & 127;
            float4 v = *reinterpret_cast<const float4*>(
                x + (size_t)(c0 + n) * SDIM + t4 * 4);
            *reinterpret_cast<float4*>(xs + n * XROW + t4 * 4) = v;
        }
    }
    // ---- zero h buffer 0 (hi0 + lo0); buffer 1 is written before read ----
    {
        uint4 z = {0u, 0u, 0u, 0u};
        #pragma unroll 1
        for (int idx = tid; idx < 2 * HTILE / 16; idx += NTHR)
            *reinterpret_cast<uint4*>(sm + HB_OFF + idx * 16) = z;
    }

    // ---- gather W_hh fragments: hi -> registers, lo -> SMEM (frag order) ----
    uint32_t whi[64];                    // [kk][4] A-fragments of W_hi
    {
        const float* Wr0 = W_hh + (size_t)r0 * HDIM;
        const float* Wr1 = W_hh + (size_t)r1 * HDIM;
        char* wlo_base = sm + WLO_OFF + ((size_t)w * 16 * 32 + lane) * 16;
        #pragma unroll
        for (int kk = 0; kk < 16; ++kk) {
            int cl = kk * 16 + 2 * tIG;  // low-k pair col
            int ch = cl + 8;             // high-k pair col
            float2 w00 = *reinterpret_cast<const float2*>(Wr0 + cl);
            float2 w10 = *reinterpret_cast<const float2*>(Wr1 + cl);
            float2 w01 = *reinterpret_cast<const float2*>(Wr0 + ch);
            float2 w11 = *reinterpret_cast<const float2*>(Wr1 + ch);
            uint4 lo;
            whi[kk * 4 + 0] = split2(w00.x, w00.y, lo.x);  // a0: (r0, k low)
            whi[kk * 4 + 1] = split2(w10.x, w10.y, lo.y);  // a1: (r1, k low)
            whi[kk * 4 + 2] = split2(w01.x, w01.y, lo.z);  // a2: (r0, k high)
            whi[kk * 4 + 3] = split2(w11.x, w11.y, lo.w);  // a3: (r1, k high)
            *reinterpret_cast<uint4*>(wlo_base + (size_t)kk * 32 * 16) = lo;
        }
    }

    // epilogue constants
    const float wx0 = W_hx[r0], wx1 = W_hx[r1];
    const float bh0 = b_h[r0],  bh1 = b_h[r1];

    // ldmatrix per-thread fixed offset within an h tile:
    // mat m = lane>>3: (k-half = m&1, n-tile = m>>1); row i = lane&7
    const uint32_t lm_off = (uint32_t)((((lane >> 3) & 1) * 8 + (lane & 7)) * HROW
                                       + ((lane >> 4) * 16));
    const uint32_t hb_u32 = smu + HB_OFF;
    const uint32_t wlo_u32 = smu + WLO_OFF + ((uint32_t)(w * 16 * 32 + lane)) * 16;
    const float* xs = (const float*)(sm + XS_OFF);

    __syncthreads();

    // ======================= time loop =======================
    #pragma unroll 1
    for (int t = 0; t < SDIM; ++t) {
        const int p = t & 1;
        const uint32_t hhi = hb_u32 + (uint32_t)(p * 2 * HTILE) + lm_off;
        const uint32_t hlo = hhi + HTILE;

        float D0[4] = {0.f, 0.f, 0.f, 0.f};
        float D1[4] = {0.f, 0.f, 0.f, 0.f};

        #pragma unroll
        for (int kk = 0; kk < 16; ++kk) {
            uint4 wl4 = *reinterpret_cast<const uint4*>(
                sm + (wlo_u32 - smu) + (uint32_t)kk * 512);
            uint32_t wlo[4] = {wl4.x, wl4.y, wl4.z, wl4.w};
            uint32_t bh4[4], bl4[4];
            ldsm_x4_t(bh4, hhi + (uint32_t)kk * (16 * HROW));
            ldsm_x4_t(bl4, hlo + (uint32_t)kk * (16 * HROW));
            const uint32_t* a = whi + kk * 4;
            // n-tile 0 (cols 0-7)
            mma16816(D0, a,   bh4[0], bh4[1]);   // Whi * h_hi
            mma16816(D0, a,   bl4[0], bl4[1]);   // Whi * h_lo
            mma16816(D0, wlo, bh4[0], bh4[1]);   // Wlo * h_hi
            // n-tile 1 (cols 8-15)
            mma16816(D1, a,   bh4[2], bh4[3]);
            mma16816(D1, a,   bl4[2], bl4[3]);
            mma16816(D1, wlo, bh4[2], bh4[3]);
        }

        // ---- epilogue: +Whx*x_t + b_h, tanh, hi/lo split, store to buf p^1 ----
        const int cc = 2 * tIG;              // n-tile0 col pair base
        float x00 = xs[(cc + 0) * XROW + t];
        float x01 = xs[(cc + 1) * XROW + t];
        float x08 = xs[(cc + 8) * XROW + t];
        float x09 = xs[(cc + 9) * XROW + t];

        float t00 = tanh_fast(D0[0] + fmaf(wx0, x00, bh0));
        float t01 = tanh_fast(D0[1] + fmaf(wx0, x01, bh0));
        float t10 = tanh_fast(D0[2] + fmaf(wx1, x00, bh1));
        float t11 = tanh_fast(D0[3] + fmaf(wx1, x01, bh1));
        float u00 = tanh_fast(D1[0] + fmaf(wx0, x08, bh0));
        float u01 = tanh_fast(D1[1] + fmaf(wx0, x09, bh0));
        float u10 = tanh_fast(D1[2] + fmaf(wx1, x08, bh1));
        float u11 = tanh_fast(D1[3] + fmaf(wx1, x09, bh1));

        char* ohi = sm + HB_OFF + (p ^ 1) * 2 * HTILE;
        char* olo = ohi + HTILE;
        uint32_t lo;
        uint32_t hi;
        hi = split2(t00, t01, lo);
        *reinterpret_cast<uint32_t*>(ohi + r0 * HROW + 4 * tIG) = hi;
        *reinterpret_cast<uint32_t*>(olo + r0 * HROW + 4 * tIG) = lo;
        hi = split2(t10, t11, lo);
        *reinterpret_cast<uint32_t*>(ohi + r1 * HROW + 4 * tIG) = hi;
        *reinterpret_cast<uint32_t*>(olo + r1 * HROW + 4 * tIG) = lo;
        hi = split2(u00, u01, lo);
        *reinterpret_cast<uint32_t*>(ohi + r0 * HROW + 16 + 4 * tIG) = hi;
        *reinterpret_cast<uint32_t*>(olo + r0 * HROW + 16 + 4 * tIG) = lo;
        hi = split2(u10, u11, lo);
        *reinterpret_cast<uint32_t*>(ohi + r1 * HROW + 16 + 4 * tIG) = hi;
        *reinterpret_cast<uint32_t*>(olo + r1 * HROW + 16 + 4 * tIG) = lo;

        __syncthreads();
    }

    // ======================= final projection =======================
    // h_final in buffer 0 ([k][n] hi+lo).  out[b][c] = W_ph[c,:]·h[:,b] + b_p[c]
    if (tid < BT * CDIM) {
        const int b = tid / CDIM, c = tid % CDIM;
        const char* hb = sm + HB_OFF;
        const char* lb = hb + HTILE;
        float s = b_p[c];
        #pragma unroll 4
        for (int i = 0; i < HDIM; ++i) {
            float h = __bfloat162float(*reinterpret_cast<const __nv_bfloat16*>(
                          hb + i * HROW + 2 * b))
                    + __bfloat162float(*reinterpret_cast<const __nv_bfloat16*>(
                          lb + i * HROW + 2 * b));
            s += W_ph[c * HDIM + i] * h;
        }
        out[(size_t)(c0 + b) * CDIM + c] = s;
    }
}

extern "C" void kernel_launch(void* const* d_in, const int* in_sizes, int n_in,
                              void* d_out, int out_size)
{
    const float* x    = (const float*)d_in[0];
    const float* W_hx = (const float*)d_in[1];
    const float* W_hh = (const float*)d_in[2];
    const float* W_ph = (const float*)d_in[3];
    const float* b_h  = (const float*)d_in[4];
    const float* b_p  = (const float*)d_in[5];
    float* out = (float*)d_out;

    cudaFuncSetAttribute(rnn_hmma_kernel,
                         cudaFuncAttributeMaxDynamicSharedMemorySize, SMEM_SZ);
    rnn_hmma_kernel<<<NCTA, NTHR, SMEM_SZ>>>(x, W_hx, W_hh, W_ph, b_h, b_p, out);
}

// round 4
// speedup vs baseline: 4.8589x; 1.0178x over previous
#include <cuda_runtime.h>
#include <cuda_bf16.h>
#include <cstdint>

// ============================ problem constants ============================
#define HDIM 256
#define SDIM 512
#define BDIM 2048
#define CDIM 10
#define BT   16                 // batch columns per CTA (N)
#define NCTA (BDIM / BT)        // 128
#define NTHR 256                // 8 warps, each owns m=32 (two m16 tiles)

// ============================ SMEM layout (bytes) ==========================
// Wlo fragments: [8 warps][2 tiles][16 ksteps][32 lanes][16B] = 131072 B
#define WLO_OFF 0
#define WLO_SZ  131072
// h tiles, [k=256][n=16] bf16, row stride 48B (16B-aligned for ldmatrix):
//   hi0, lo0, hi1, lo1
#define HROW    48
#define HTILE   (HDIM * HROW)            // 12288
#define HB_OFF  WLO_SZ                   // 131072
#define HB_SZ   (4 * HTILE)              // 49152
// x staged [n=16][t=512] fp32, row pad 516 floats
#define XROW    516
#define XS_OFF  (HB_OFF + HB_SZ)         // 180224
#define XS_SZ   (BT * XROW * 4)          // 33024
#define SMEM_SZ (XS_OFF + XS_SZ)         // 213248

// ============================ device helpers ===============================
__device__ __forceinline__ uint32_t smem_u32(const void* p) {
    return (uint32_t)__cvta_generic_to_shared(p);
}

__device__ __forceinline__ void ldsm_x4_t(uint32_t* r, uint32_t addr) {
    asm volatile("ldmatrix.sync.aligned.m8n8.x4.trans.shared.b16 "
                 "{%0,%1,%2,%3}, [%4];"
                 : "=r"(r[0]), "=r"(r[1]), "=r"(r[2]), "=r"(r[3])
                 : "r"(addr));
}

__device__ __forceinline__ void mma16816(float* d, const uint32_t* a,
                                         uint32_t b0, uint32_t b1) {
    asm volatile("mma.sync.aligned.m16n8k16.row.col.f32.bf16.bf16.f32 "
                 "{%0,%1,%2,%3},{%4,%5,%6,%7},{%8,%9},{%0,%1,%2,%3};"
                 : "+f"(d[0]), "+f"(d[1]), "+f"(d[2]), "+f"(d[3])
                 : "r"(a[0]), "r"(a[1]), "r"(a[2]), "r"(a[3]),
                   "r"(b0), "r"(b1));
}

__device__ __forceinline__ uint32_t pack_bf2(__nv_bfloat16 a, __nv_bfloat16 b) {
    return (uint32_t)__bfloat16_as_ushort(a) |
           ((uint32_t)__bfloat16_as_ushort(b) << 16);
}

// split float pair into bf16-hi pair (returned) and bf16-lo pair (out param)
__device__ __forceinline__ uint32_t split2(float x, float y, uint32_t& lo) {
    __nv_bfloat16 xh = __float2bfloat16(x), yh = __float2bfloat16(y);
    float xl = x - __bfloat162float(xh), yl = y - __bfloat162float(yh);
    lo = pack_bf2(__float2bfloat16(xl), __float2bfloat16(yl));
    return pack_bf2(xh, yh);
}

__device__ __forceinline__ float tanh_fast(float x) {
    x = fminf(fmaxf(x, -10.0f), 10.0f);
    float e = __expf(2.0f * x);
    return __fdividef(e - 1.0f, e + 1.0f);
}

// ============================ kernel =======================================
extern "C" __global__ void __launch_bounds__(NTHR, 1)
rnn_hmma8_kernel(const float* __restrict__ x,
                 const float* __restrict__ W_hx,
                 const float* __restrict__ W_hh,
                 const float* __restrict__ W_ph,
                 const float* __restrict__ b_h,
                 const float* __restrict__ b_p,
                 float* __restrict__ out)
{
    extern __shared__ char sm[];
    const uint32_t smu = smem_u32(sm);

    const int tid  = threadIdx.x;
    const int w    = tid >> 5;          // warp id, owns rows 32w..32w+31
    const int lane = tid & 31;
    const int g    = lane >> 2;         // groupID 0..7
    const int tIG  = lane & 3;          // thread-in-group 0..3
    const int m0   = w * 32;
    const int c0   = blockIdx.x * BT;   // first batch column of this CTA

    // ---- stage x: xs[n][t] fp32, coalesced float4 ----
    {
        float* xs = (float*)(sm + XS_OFF);
        #pragma unroll 1
        for (int idx = tid; idx < BT * SDIM / 4; idx += NTHR) {
            int n = idx >> 7, t4 = idx & 127;
            float4 v = *reinterpret_cast<const float4*>(
                x + (size_t)(c0 + n) * SDIM + t4 * 4);
            *reinterpret_cast<float4*>(xs + n * XROW + t4 * 4) = v;
        }
    }
    // ---- zero h buffer 0 (hi0 + lo0); buffer 1 is written before read ----
    {
        uint4 z = {0u, 0u, 0u, 0u};
        #pragma unroll 1
        for (int idx = tid; idx < 2 * HTILE / 16; idx += NTHR)
            *reinterpret_cast<uint4*>(sm + HB_OFF + idx * 16) = z;
    }

    // ---- gather W_hh fragments: hi -> regs (both tiles), lo -> SMEM ----
    uint32_t whi[128];                   // [tile][kk][4]
    {
        #pragma unroll
        for (int tl = 0; tl < 2; ++tl) {
            const int rA = m0 + tl * 16 + g;
            const int rB = rA + 8;
            const float* Wr0 = W_hh + (size_t)rA * HDIM;
            const float* Wr1 = W_hh + (size_t)rB * HDIM;
            char* wlo_base = sm + WLO_OFF +
                ((size_t)(w * 2 + tl) * 16 * 32 + lane) * 16;
            #pragma unroll
            for (int kk = 0; kk < 16; ++kk) {
                int cl = kk * 16 + 2 * tIG;
                int ch = cl + 8;
                float2 w00 = *reinterpret_cast<const float2*>(Wr0 + cl);
                float2 w10 = *reinterpret_cast<const float2*>(Wr1 + cl);
                float2 w01 = *reinterpret_cast<const float2*>(Wr0 + ch);
                float2 w11 = *reinterpret_cast<const float2*>(Wr1 + ch);
                uint4 lo;
                whi[tl * 64 + kk * 4 + 0] = split2(w00.x, w00.y, lo.x);
                whi[tl * 64 + kk * 4 + 1] = split2(w10.x, w10.y, lo.y);
                whi[tl * 64 + kk * 4 + 2] = split2(w01.x, w01.y, lo.z);
                whi[tl * 64 + kk * 4 + 3] = split2(w11.x, w11.y, lo.w);
                *reinterpret_cast<uint4*>(wlo_base + (size_t)kk * 32 * 16) = lo;
            }
        }
    }

    // epilogue constants (4 row positions this thread writes)
    const int rA0 = m0 + g, rA1 = rA0 + 8;        // tile 0 rows
    const int rB0 = rA0 + 16, rB1 = rA0 + 24;     // tile 1 rows
    const float wxA0 = W_hx[rA0], wxA1 = W_hx[rA1];
    const float wxB0 = W_hx[rB0], wxB1 = W_hx[rB1];
    const float bhA0 = b_h[rA0],  bhA1 = b_h[rA1];
    const float bhB0 = b_h[rB0],  bhB1 = b_h[rB1];

    // ldmatrix per-thread fixed offset within an h tile
    const uint32_t lm_off = (uint32_t)((((lane >> 3) & 1) * 8 + (lane & 7)) * HROW
                                       + ((lane >> 4) * 16));
    const uint32_t hb_u32 = smu + HB_OFF;
    const uint32_t wlo_u32_0 = smu + WLO_OFF +
        ((uint32_t)((w * 2 + 0) * 16 * 32 + lane)) * 16;
    const uint32_t wlo_u32_1 = wlo_u32_0 + 16 * 32 * 16;
    const float* xs = (const float*)(sm + XS_OFF);

    __syncthreads();

    // ======================= time loop =======================
    #pragma unroll 1
    for (int t = 0; t < SDIM; ++t) {
        const int p = t & 1;
        const uint32_t hhi = hb_u32 + (uint32_t)(p * 2 * HTILE) + lm_off;
        const uint32_t hlo = hhi + HTILE;

        float DA0[4] = {0.f,0.f,0.f,0.f};   // tile0, n-tile0
        float DA1[4] = {0.f,0.f,0.f,0.f};   // tile0, n-tile1
        float DB0[4] = {0.f,0.f,0.f,0.f};   // tile1, n-tile0
        float DB1[4] = {0.f,0.f,0.f,0.f};   // tile1, n-tile1

        #pragma unroll
        for (int kk = 0; kk < 16; ++kk) {
            uint32_t bh4[4], bl4[4];
            ldsm_x4_t(bh4, hhi + (uint32_t)kk * (16 * HROW));
            ldsm_x4_t(bl4, hlo + (uint32_t)kk * (16 * HROW));
            uint4 wlA = *reinterpret_cast<const uint4*>(
                sm + (wlo_u32_0 - smu) + (uint32_t)kk * 512);
            uint4 wlB = *reinterpret_cast<const uint4*>(
                sm + (wlo_u32_1 - smu) + (uint32_t)kk * 512);
            uint32_t wloA[4] = {wlA.x, wlA.y, wlA.z, wlA.w};
            uint32_t wloB[4] = {wlB.x, wlB.y, wlB.z, wlB.w};
            const uint32_t* aA = whi + kk * 4;        // tile 0 W_hi
            const uint32_t* aB = whi + 64 + kk * 4;   // tile 1 W_hi

            // tile 0
            mma16816(DA0, aA,   bh4[0], bh4[1]);
            mma16816(DA0, aA,   bl4[0], bl4[1]);
            mma16816(DA0, wloA, bh4[0], bh4[1]);
            mma16816(DA1, aA,   bh4[2], bh4[3]);
            mma16816(DA1, aA,   bl4[2], bl4[3]);
            mma16816(DA1, wloA, bh4[2], bh4[3]);
            // tile 1
            mma16816(DB0, aB,   bh4[0], bh4[1]);
            mma16816(DB0, aB,   bl4[0], bl4[1]);
            mma16816(DB0, wloB, bh4[0], bh4[1]);
            mma16816(DB1, aB,   bh4[2], bh4[3]);
            mma16816(DB1, aB,   bl4[2], bl4[3]);
            mma16816(DB1, wloB, bh4[2], bh4[3]);
        }

        // ---- epilogue: +Whx*x_t + b_h, tanh, hi/lo split, store to buf p^1 ----
        const int cc = 2 * tIG;
        float x00 = xs[(cc + 0) * XROW + t];
        float x01 = xs[(cc + 1) * XROW + t];
        float x08 = xs[(cc + 8) * XROW + t];
        float x09 = xs[(cc + 9) * XROW + t];

        char* ohi = sm + HB_OFF + (p ^ 1) * 2 * HTILE;
        char* olo = ohi + HTILE;
        uint32_t hi, lo;

        // tile 0
        hi = split2(tanh_fast(DA0[0] + fmaf(wxA0, x00, bhA0)),
                    tanh_fast(DA0[1] + fmaf(wxA0, x01, bhA0)), lo);
        *reinterpret_cast<uint32_t*>(ohi + rA0 * HROW + 4 * tIG) = hi;
        *reinterpret_cast<uint32_t*>(olo + rA0 * HROW + 4 * tIG) = lo;
        hi = split2(tanh_fast(DA0[2] + fmaf(wxA1, x00, bhA1)),
                    tanh_fast(DA0[3] + fmaf(wxA1, x01, bhA1)), lo);
        *reinterpret_cast<uint32_t*>(ohi + rA1 * HROW + 4 * tIG) = hi;
        *reinterpret_cast<uint32_t*>(olo + rA1 * HROW + 4 * tIG) = lo;
        hi = split2(tanh_fast(DA1[0] + fmaf(wxA0, x08, bhA0)),
                    tanh_fast(DA1[1] + fmaf(wxA0, x09, bhA0)), lo);
        *reinterpret_cast<uint32_t*>(ohi + rA0 * HROW + 16 + 4 * tIG) = hi;
        *reinterpret_cast<uint32_t*>(olo + rA0 * HROW + 16 + 4 * tIG) = lo;
        hi = split2(tanh_fast(DA1[2] + fmaf(wxA1, x08, bhA1)),
                    tanh_fast(DA1[3] + fmaf(wxA1, x09, bhA1)), lo);
        *reinterpret_cast<uint32_t*>(ohi + rA1 * HROW + 16 + 4 * tIG) = hi;
        *reinterpret_cast<uint32_t*>(olo + rA1 * HROW + 16 + 4 * tIG) = lo;
        // tile 1
        hi = split2(tanh_fast(DB0[0] + fmaf(wxB0, x00, bhB0)),
                    tanh_fast(DB0[1] + fmaf(wxB0, x01, bhB0)), lo);
        *reinterpret_cast<uint32_t*>(ohi + rB0 * HROW + 4 * tIG) = hi;
        *reinterpret_cast<uint32_t*>(olo + rB0 * HROW + 4 * tIG) = lo;
        hi = split2(tanh_fast(DB0[2] + fmaf(wxB1, x00, bhB1)),
                    tanh_fast(DB0[3] + fmaf(wxB1, x01, bhB1)), lo);
        *reinterpret_cast<uint32_t*>(ohi + rB1 * HROW + 4 * tIG) = hi;
        *reinterpret_cast<uint32_t*>(olo + rB1 * HROW + 4 * tIG) = lo;
        hi = split2(tanh_fast(DB1[0] + fmaf(wxB0, x08, bhB0)),
                    tanh_fast(DB1[1] + fmaf(wxB0, x09, bhB0)), lo);
        *reinterpret_cast<uint32_t*>(ohi + rB0 * HROW + 16 + 4 * tIG) = hi;
        *reinterpret_cast<uint32_t*>(olo + rB0 * HROW + 16 + 4 * tIG) = lo;
        hi = split2(tanh_fast(DB1[2] + fmaf(wxB1, x08, bhB1)),
                    tanh_fast(DB1[3] + fmaf(wxB1, x09, bhB1)), lo);
        *reinterpret_cast<uint32_t*>(ohi + rB1 * HROW + 16 + 4 * tIG) = hi;
        *reinterpret_cast<uint32_t*>(olo + rB1 * HROW + 16 + 4 * tIG) = lo;

        __syncthreads();
    }

    // ======================= final projection =======================
    if (tid < BT * CDIM) {
        const int b = tid / CDIM, c = tid % CDIM;
        const char* hb = sm + HB_OFF;
        const char* lb = hb + HTILE;
        float s = b_p[c];
        #pragma unroll 4
        for (int i = 0; i < HDIM; ++i) {
            float h = __bfloat162float(*reinterpret_cast<const __nv_bfloat16*>(
                          hb + i * HROW + 2 * b))
                    + __bfloat162float(*reinterpret_cast<const __nv_bfloat16*>(
                          lb + i * HROW + 2 * b));
            s += W_ph[c * HDIM + i] * h;
        }
        out[(size_t)(c0 + b) * CDIM + c] = s;
    }
}

extern "C" void kernel_launch(void* const* d_in, const int* in_sizes, int n_in,
                              void* d_out, int out_size)
{
    const float* x    = (const float*)d_in[0];
    const float* W_hx = (const float*)d_in[1];
    const float* W_hh = (const float*)d_in[2];
    const float* W_ph = (const float*)d_in[3];
    const float* b_h  = (const float*)d_in[4];
    const float* b_p  = (const float*)d_in[5];
    float* out = (float*)d_out;

    cudaFuncSetAttribute(rnn_hmma8_kernel,
                         cudaFuncAttributeMaxDynamicSharedMemorySize, SMEM_SZ);
    rnn_hmma8_kernel<<<NCTA, NTHR, SMEM_SZ>>>(x, W_hx, W_hh, W_ph, b_h, b_p, out);
}